// round 14
// baseline (speedup 1.0000x reference)
#include <cuda_runtime.h>
#include <cstdint>

// SpecialSpmmFinal: out[src[e], :] += edge_w[e, :] for e in [0, E)
// N=100000, E=3200000, F=16, fp32. src = edge[0] (first E ints of [2,E]).
//
// R12: R7/R10 scatter (lane-transposed, 2 quarter-pieces/thread — measured
// REDG lane-issue floor) + Programmatic Dependent Launch: the scatter kernel
// launches while the zero kernel drains, front-batches its independent loads,
// and only grid-dependency-syncs before the first atomic. Hides the zeroing
// pass + launch gap under the scatter's first-wave load latency.

#define N_NODES 100000
#define N_EDGES 3200000
#define FEAT 16
#define NQUARTERS (N_EDGES * 4)       // 12,800,000 quarter-rows
#define HALFQ (NQUARTERS / 2)         // 6,400,000

// ---------------------------------------------------------------------------
// Zero the output (harness poisons d_out with 0xAA). Triggers programmatic
// launch completion so the dependent scatter kernel may begin launching.
// ---------------------------------------------------------------------------
__global__ void __launch_bounds__(512)
zero_out_kernel(float4* __restrict__ out, int n4) {
    int i = blockIdx.x * blockDim.x + threadIdx.x;
    if (i < n4) out[i] = make_float4(0.f, 0.f, 0.f, 0.f);
    cudaTriggerProgrammaticLaunchCompletion();
}

// ---------------------------------------------------------------------------
// Fire-and-forget 16B float reduction (no "memory" clobber: dest is never
// read in this kernel; nothing may serialize against it).
// ---------------------------------------------------------------------------
__device__ __forceinline__ void red_add_v4(float* dst, float4 v) {
    asm volatile(
        "red.global.add.v4.f32 [%0], {%1, %2, %3, %4};"
        :: "l"(dst), "f"(v.x), "f"(v.y), "f"(v.z), "f"(v.w));
}

// Evict-first 128-bit load (edge_w is touch-once; keep out[] hot in L2).
__device__ __forceinline__ float4 ldcs4(const float4* p) {
    float4 v;
    asm volatile("ld.global.cs.v4.f32 {%0, %1, %2, %3}, [%4];"
                 : "=f"(v.x), "=f"(v.y), "=f"(v.z), "=f"(v.w)
                 : "l"(p));
    return v;
}

// ---------------------------------------------------------------------------
// Lane-transposed scatter-add, 2 pieces per thread (measured optimum).
// Thread t handles quarter-rows t and t+HALFQ:
//   piece q: edge q/4, j = q%4
//   load : w[q]                 (float4; warp = 512 contiguous bytes)
//   index: src[q/4]             (4-lane broadcast)
//   RED  : out[s*16 + j*4]      (warp = 8 nodes x 64 contiguous bytes)
// Loads are issued BEFORE cudaGridDependencySynchronize(): they don't depend
// on the zeroed output, so they overlap with the predecessor kernel.
// ---------------------------------------------------------------------------
__global__ void __launch_bounds__(256)
scatter_add_kernel(const int* __restrict__ src,
                   const float4* __restrict__ w,   // [E*4] float4 view of [E,16]
                   float* __restrict__ out) {      // [N,16] f32
    int t = blockIdx.x * blockDim.x + threadIdx.x;

    int    s0 = 0, s1 = 0;
    float4 v0, v1;
    const bool active = (t < HALFQ);
    const int q0 = t;
    const int q1 = t + HALFQ;

    if (active) {
        // Independent of the zero pass — issue immediately.
        s0 = src[q0 >> 2];
        s1 = src[q1 >> 2];
        v0 = ldcs4(w + q0);
        v1 = ldcs4(w + q1);
    }

    // Wait for the zero kernel's writes to be visible before any atomic.
    cudaGridDependencySynchronize();

    if (active) {
        red_add_v4(out + (size_t)s0 * FEAT + (q0 & 3) * 4, v0);
        red_add_v4(out + (size_t)s1 * FEAT + (q1 & 3) * 4, v1);
    }
}

// ---------------------------------------------------------------------------
// kernel_launch
// Inputs (metadata order): edge [2,E] int32, edge_w [E,16] f32, then scalars.
// ---------------------------------------------------------------------------
extern "C" void kernel_launch(void* const* d_in, const int* in_sizes, int n_in,
                              void* d_out, int out_size) {
    const int*    src    = (const int*)d_in[0];     // edge[0] = first E ints
    const float4* edge_w = (const float4*)d_in[1];
    float*        out    = (float*)d_out;

    (void)in_sizes; (void)n_in; (void)out_size;

    // 1) zero pass (signals programmatic completion per block)
    {
        int n4 = N_NODES * FEAT / 4;                // 400000
        int threads = 512;
        int blocks = (n4 + threads - 1) / threads;  // 782
        zero_out_kernel<<<blocks, threads>>>((float4*)out, n4);
    }

    // 2) scatter, launched with Programmatic Stream Serialization so it
    //    overlaps the tail of the zero pass.
    {
        int threads = 256;
        int blocks = (HALFQ + threads - 1) / threads;  // 25000

        cudaLaunchConfig_t cfg = {};
        cfg.gridDim  = dim3(blocks, 1, 1);
        cfg.blockDim = dim3(threads, 1, 1);
        cfg.dynamicSmemBytes = 0;
        cfg.stream = 0;

        cudaLaunchAttribute attr[1];
        attr[0].id = cudaLaunchAttributeProgrammaticStreamSerialization;
        attr[0].val.programmaticStreamSerializationAllowed = 1;
        cfg.attrs = attr;
        cfg.numAttrs = 1;

        cudaLaunchKernelEx(&cfg, scatter_add_kernel, src, edge_w, out);
    }
}